// round 3
// baseline (speedup 1.0000x reference)
#include <cuda_runtime.h>
#include <math.h>

#define NB 32
#define NA 8400
#define NM 50
#define NC 80
#define KTOP 10
#define PRED_DIM 85
#define MAXF 2048
#define BIGC 1e15f
#define INPUT_SZ 640.0f
#define PI_F 3.14159265358979323846f

// ---------------- scratch (static device arrays) ----------------
__device__ float4 g_geom[NA];               // xc, yc, cd, unused
__device__ int    g_nf[NB];                 // filtered-anchor count per image
__device__ int    g_flist[NB*MAXF];         // compact slot -> original anchor id
__device__ int    g_cidx[NB*NA];            // anchor -> compact slot (-1 if unfiltered)
__device__ float  g_s1mc[NB*MAXF];
__device__ float  g_sobjc[NB*MAXF];
__device__ float  g_costc[NB*NM*MAXF];      // 13.1 MB compact cost matrix
__device__ int    g_dynk[NB*NM];
__device__ int    g_topidx[NB*NM*KTOP];     // original anchor ids
__device__ int    g_amg[NB*NA];
__device__ int    g_msum[NB*NA];
__device__ int    g_matched[NB*NA];
__device__ float  g_acc[NB*4];              // obj_sum, cls_sum, box_sum, npos

// ---------------- helpers ----------------
__device__ __forceinline__ void anchor_geom(int a, float& xc, float& yc, float& cd){
    if (a < 6400){
        int y = a / 80, x = a - y*80;
        xc = (x + 0.5f)*8.f;  yc = (y + 0.5f)*8.f;  cd = 12.f;
    } else if (a < 8000){
        int i = a - 6400; int y = i / 40, x = i - y*40;
        xc = (x + 0.5f)*16.f; yc = (y + 0.5f)*16.f; cd = 24.f;
    } else {
        int i = a - 8000; int y = i / 20, x = i - y*20;
        xc = (x + 0.5f)*32.f; yc = (y + 0.5f)*32.f; cd = 48.f;
    }
}

__device__ __forceinline__ float sigmoidf_(float x){
    if (x >= 0.f) return 1.f/(1.f+expf(-x));
    float e = expf(x); return e/(1.f+e);
}

__device__ __forceinline__ float bce_logits(float x, float t){
    return fmaxf(x, 0.f) - x*t + log1pf(expf(-fabsf(x)));
}

__device__ __forceinline__ float ciou_loss(float px,float py,float pw,float ph,
                                           float gx,float gy,float gw,float gh){
    const float eps = 1e-7f;
    float px1=px-pw*0.5f, py1=py-ph*0.5f, px2=px+pw*0.5f, py2=py+ph*0.5f;
    float gx1=gx-gw*0.5f, gy1=gy-gh*0.5f, gx2=gx+gw*0.5f, gy2=gy+gh*0.5f;
    float iw = fmaxf(fminf(px2,gx2)-fmaxf(px1,gx1), 0.f);
    float ih = fmaxf(fminf(py2,gy2)-fmaxf(py1,gy1), 0.f);
    float inter = iw*ih;
    float uni = pw*ph + gw*gh - inter + eps;
    float iou = inter/uni;
    float cw = fmaxf(px2,gx2)-fminf(px1,gx1);
    float ch = fmaxf(py2,gy2)-fminf(py1,gy1);
    float c2 = cw*cw + ch*ch + eps;
    float rho2 = (gx-px)*(gx-px) + (gy-py)*(gy-py);
    float d = atanf(gw/(gh+eps)) - atanf(pw/(ph+eps));
    float v = (4.0f/(PI_F*PI_F))*d*d;
    float alpha = v/(1.f-iou+v+eps);
    return 1.f - iou + rho2/c2 + alpha*v;
}

// ---------------- kernel 0: init accumulators + geometry table ----------------
__global__ void initK(){
    int t = blockIdx.x*blockDim.x + threadIdx.x;
    if (t < NB*NA){ g_amg[t]=0; g_msum[t]=0; }
    if (t < NB*4)  g_acc[t]=0.f;
    if (t < NB)    g_nf[t]=0;
    if (t < NA){
        float xc, yc, cd; anchor_geom(t, xc, yc, cd);
        g_geom[t] = make_float4(xc, yc, cd, 0.f);
    }
}

// ---------------- kernel 1: geometry filter + compaction + s1m/sobj for filtered ----------------
__global__ void perAnchorK(const float* __restrict__ pred, const float* __restrict__ tgt){
    int b = blockIdx.y;
    int a = blockIdx.x*blockDim.x + threadIdx.x;
    __shared__ float sgx[NM], sgy[NM];
    __shared__ int   svalid[NM];
    for (int i=threadIdx.x; i<NM; i+=blockDim.x){
        float c0 = tgt[(b*NM+i)*5];
        svalid[i] = c0 >= 0.f;
        sgx[i] = tgt[(b*NM+i)*5+1]*INPUT_SZ;
        sgy[i] = tgt[(b*NM+i)*5+2]*INPUT_SZ;
    }
    __syncthreads();
    if (a >= NA) return;
    float xc, yc, cd; anchor_geom(a, xc, yc, cd);
    bool any = false;
    for (int m=0; m<NM; m++){
        if (!svalid[m]) continue;
        // exact reference rounding order
        float c_l = xc - (sgx[m] - cd);
        float c_r = (sgx[m] + cd) - xc;
        float c_t = yc - (sgy[m] - cd);
        float c_b = (sgy[m] + cd) - yc;
        if (fminf(fminf(c_l,c_r), fminf(c_t,c_b)) > 0.f){ any = true; break; }
    }
    int idx = b*NA + a;
    if (!any){ g_cidx[idx] = -1; return; }
    int slot = atomicAdd(&g_nf[b], 1);
    if (slot >= MAXF){ g_cidx[idx] = -1; return; }   // impossible (<=1350), safety
    g_flist[b*MAXF + slot] = a;
    g_cidx[idx] = slot;
    const float* pr = pred + ((size_t)b*NA + a)*PRED_DIM;
    float sobj = sigmoidf_(pr[4]);
    float s1m = 0.f;
    #pragma unroll 4
    for (int c=0;c<NC;c++){
        float sc = sigmoidf_(pr[5+c]);
        float p = sqrtf(sc*sobj);
        s1m += fmaxf(log1pf(-p), -100.f);
    }
    g_sobjc[b*MAXF + slot] = sobj;
    g_s1mc[b*MAXF + slot]  = s1m;
}

// ---------------- kernel 2: compact cost + fused row-wise top-k ----------------
__global__ void costK(const float* __restrict__ pred, const float* __restrict__ tgt){
    int bm = blockIdx.x;
    int b = bm / NM, m = bm - b*NM;
    int t = threadIdx.x;                 // 128 threads
    const float* tr = tgt + (b*NM+m)*5;
    float c0 = tr[0];
    if (c0 < 0.f){ if (t==0) g_dynk[bm] = 0; return; }
    int gcls = (int)fminf(fmaxf(c0, 0.f), (float)(NC-1));
    float gx = tr[1]*INPUT_SZ, gy = tr[2]*INPUT_SZ, gw = tr[3]*INPUT_SZ, gh = tr[4]*INPUT_SZ;
    float areag = gw*gh;
    int nf = g_nf[b];
    if (nf > MAXF) nf = MAXF;

    float cv[KTOP]; int ci[KTOP]; float iv[KTOP];
    #pragma unroll
    for (int k=0;k<KTOP;k++){ cv[k]=3.4e38f; ci[k]=0x7fffffff; iv[k]=0.f; }

    const float* s1mp = g_s1mc + b*MAXF;
    const float* sobp = g_sobjc + b*MAXF;
    const int*   flst = g_flist + b*MAXF;
    float* crow = g_costc + (size_t)bm * MAXF;

    for (int i = t; i < nf; i += 128){
        int a = flst[i];
        float4 gg = g_geom[a];
        // exact reference rounding order for the center test
        float c_l = gg.x - (gx - gg.z);
        float c_r = (gx + gg.z) - gg.x;
        float c_t = gg.y - (gy - gg.z);
        float c_b = (gy + gg.z) - gg.y;
        bool in_c = fminf(fminf(c_l,c_r), fminf(c_t,c_b)) > 0.f;

        const float* pr = pred + ((size_t)b*NA + a)*PRED_DIM;
        float px=pr[0], py=pr[1], pw=pr[2], ph=pr[3];
        float tlx = fmaxf(gx-gw*0.5f, px-pw*0.5f);
        float tly = fmaxf(gy-gh*0.5f, py-ph*0.5f);
        float brx = fminf(gx+gw*0.5f, px+pw*0.5f);
        float bry = fminf(gy+gh*0.5f, py+ph*0.5f);
        float iou = 0.f;
        if (tlx<brx && tly<bry){
            float ai = (brx-tlx)*(bry-tly);
            iou = ai/(areag + pw*ph - ai);
        }
        float iou_cost = -logf(iou + 1e-8f);
        float sc = sigmoidf_(pr[5+gcls]);
        float p = sqrtf(sc * sobp[i]);
        float lp  = fmaxf(logf(p),     -100.f);
        float l1m = fmaxf(log1pf(-p), -100.f);
        float cls_cost = -lp - (s1mp[i] - l1m);
        float cost = cls_cost + 3.f*iou_cost + (in_c ? 0.f : 1e6f);
        crow[i] = cost;

        // ascending cost top-10 (tie-break: lower original anchor index)
        if (cost < cv[KTOP-1] || (cost == cv[KTOP-1] && a < ci[KTOP-1])){
            cv[KTOP-1]=cost; ci[KTOP-1]=a;
            #pragma unroll
            for (int j=KTOP-1;j>0;j--){
                bool sw = cv[j] < cv[j-1] || (cv[j]==cv[j-1] && ci[j]<ci[j-1]);
                if (!sw) break;
                float tv=cv[j]; cv[j]=cv[j-1]; cv[j-1]=tv;
                int ti=ci[j]; ci[j]=ci[j-1]; ci[j-1]=ti;
            }
        }
        // descending iou top-10 (values only)
        if (iou > iv[KTOP-1]){
            iv[KTOP-1]=iou;
            #pragma unroll
            for (int j=KTOP-1;j>0;j--){
                if (iv[j] <= iv[j-1]) break;
                float tv=iv[j]; iv[j]=iv[j-1]; iv[j-1]=tv;
            }
        }
    }

    __shared__ float scv[128][KTOP];
    __shared__ int   sci[128][KTOP];
    __shared__ float siv[128][KTOP];
    #pragma unroll
    for (int k=0;k<KTOP;k++){ scv[t][k]=cv[k]; sci[t][k]=ci[k]; siv[t][k]=iv[k]; }

    for (int s=64; s>=1; s>>=1){
        __syncthreads();
        if (t < s){
            float av[KTOP], bv[KTOP], a2[KTOP], b2[KTOP]; int ai[KTOP], bi[KTOP];
            #pragma unroll
            for (int k=0;k<KTOP;k++){
                av[k]=scv[t][k];   ai[k]=sci[t][k];
                bv[k]=scv[t+s][k]; bi[k]=sci[t+s][k];
                a2[k]=siv[t][k];   b2[k]=siv[t+s][k];
            }
            int i=0, j=0;
            #pragma unroll
            for (int k=0;k<KTOP;k++){
                bool ta = av[i] < bv[j] || (av[i]==bv[j] && ai[i] < bi[j]);
                if (ta){ scv[t][k]=av[i]; sci[t][k]=ai[i]; i++; }
                else   { scv[t][k]=bv[j]; sci[t][k]=bi[j]; j++; }
            }
            i=0; j=0;
            #pragma unroll
            for (int k=0;k<KTOP;k++){
                if (a2[i] >= b2[j]) { siv[t][k]=a2[i]; i++; }
                else                { siv[t][k]=b2[j]; j++; }
            }
        }
    }
    __syncthreads();
    if (t==0){
        float sum = 0.f;
        #pragma unroll
        for (int k=0;k<KTOP;k++) sum += siv[0][k];
        int dk = (int)sum;                       // trunc, matches astype(int32)
        dk = dk < 1 ? 1 : (dk > KTOP ? KTOP : dk);
        g_dynk[bm] = dk;
        #pragma unroll
        for (int k=0;k<KTOP;k++) g_topidx[bm*KTOP+k] = sci[0][k];
    }
}

// ---------------- kernel 3: scatter selections ----------------
__global__ void scatterK(){
    int t = blockIdx.x*blockDim.x + threadIdx.x;
    if (t >= NB*NM*KTOP) return;
    int bm = t / KTOP, k = t - bm*KTOP;
    if (k < g_dynk[bm]){
        int a = g_topidx[t];
        if (a < 0 || a >= NA) return;   // sentinel safety
        int b = bm / NM, m = bm - b*NM;
        atomicAdd(&g_amg[b*NA + a], 1);
        atomicAdd(&g_msum[b*NA + a], m);
    }
}

// ---------------- kernel 4: resolve duplicates ----------------
__global__ void resolveK(const float* __restrict__ tgt){
    int t = blockIdx.x*blockDim.x + threadIdx.x;
    if (t >= NB*NA) return;
    int b = t / NA;
    int cnt = g_amg[t];
    int matched = -1;
    if (cnt == 1) matched = g_msum[t];
    else if (cnt > 1){
        int slot = g_cidx[t];
        float best = 3.4e38f; int bi = 0;
        for (int m=0;m<NM;m++){
            if (tgt[(b*NM+m)*5] < 0.f) continue;       // padded GT: BIG, never wins
            float c = g_costc[((size_t)(b*NM+m))*MAXF + slot];
            if (c < best){ best=c; bi=m; }             // strict <: first-min = jnp.argmin
        }
        matched = bi;
    }
    g_matched[t] = matched;
}

// ---------------- kernel 5: losses ----------------
__global__ void lossK(const float* __restrict__ pred, const float* __restrict__ tgt){
    int b = blockIdx.y;
    int a = blockIdx.x*blockDim.x + threadIdx.x;
    int t = threadIdx.x;
    __shared__ float stg[NM*5];
    for (int i=t; i<NM*5; i+=blockDim.x) stg[i]=tgt[b*NM*5+i];
    __syncthreads();
    float o=0.f, cl=0.f, bx=0.f, np=0.f;
    if (a < NA){
        const float* pr = pred + ((size_t)b*NA + a)*PRED_DIM;
        int mg = g_matched[b*NA + a];
        float tf = (mg >= 0) ? 1.f : 0.f;
        o = bce_logits(pr[4], tf);
        if (mg >= 0){
            np = 1.f;
            int gc = (int)fminf(fmaxf(stg[mg*5], 0.f), (float)(NC-1));
            #pragma unroll 4
            for (int c=0;c<NC;c++)
                cl += bce_logits(pr[5+c], (c==gc)?1.f:0.f);
            float gx=stg[mg*5+1]*INPUT_SZ, gy=stg[mg*5+2]*INPUT_SZ;
            float gw=stg[mg*5+3]*INPUT_SZ, gh=stg[mg*5+4]*INPUT_SZ;
            bx = ciou_loss(pr[0],pr[1],pr[2],pr[3], gx,gy,gw,gh);
        }
    }
    __shared__ float r0[256], r1[256], r2[256], r3[256];
    r0[t]=o; r1[t]=cl; r2[t]=bx; r3[t]=np;
    __syncthreads();
    for (int s=128; s>=1; s>>=1){
        if (t < s){ r0[t]+=r0[t+s]; r1[t]+=r1[t+s]; r2[t]+=r2[t+s]; r3[t]+=r3[t+s]; }
        __syncthreads();
    }
    if (t==0){
        atomicAdd(&g_acc[b*4+0], r0[0]);
        atomicAdd(&g_acc[b*4+1], r1[0]);
        atomicAdd(&g_acc[b*4+2], r2[0]);
        atomicAdd(&g_acc[b*4+3], r3[0]);
    }
}

// ---------------- kernel 6: final reduction ----------------
__global__ void finalK(float* __restrict__ out){
    int t = threadIdx.x;   // 32 threads, one per image
    float obj=0.f, cls=0.f, box=0.f, np=0.f;
    if (t < NB){
        np  = g_acc[t*4+3];
        obj = g_acc[t*4+0] / (float)NA;
        cls = (np > 0.f) ? g_acc[t*4+1]/(np*(float)NC) : 0.f;
        box = (np > 0.f) ? g_acc[t*4+2]/np : 0.f;
    }
    for (int s=16; s>=1; s>>=1){
        obj += __shfl_down_sync(0xffffffffu, obj, s);
        cls += __shfl_down_sync(0xffffffffu, cls, s);
        box += __shfl_down_sync(0xffffffffu, box, s);
        np  += __shfl_down_sync(0xffffffffu, np,  s);
    }
    if (t==0){
        float total = (5.f*box + obj + cls) / fmaxf(np, 1.f);
        out[0]=total; out[1]=box; out[2]=obj; out[3]=cls; out[4]=np;
    }
}

// ---------------- launch ----------------
extern "C" void kernel_launch(void* const* d_in, const int* in_sizes, int n_in,
                              void* d_out, int out_size){
    const float* pred = (const float*)d_in[0];   // [B, A, 85]
    const float* tgt  = (const float*)d_in[1];   // [B, M, 5]
    float* out = (float*)d_out;                  // 5 floats

    initK<<<(NB*NA+255)/256, 256>>>();
    dim3 gA((NA+255)/256, NB);
    perAnchorK<<<gA, 256>>>(pred, tgt);
    costK<<<NB*NM, 128>>>(pred, tgt);
    scatterK<<<(NB*NM*KTOP+255)/256, 256>>>();
    resolveK<<<(NB*NA+255)/256, 256>>>(tgt);
    lossK<<<gA, 256>>>(pred, tgt);
    finalK<<<1, 32>>>(out);
}

// round 4
// speedup vs baseline: 1.7121x; 1.7121x over previous
#include <cuda_runtime.h>
#include <math.h>

#define NB 32
#define NA 8400
#define NM 50
#define NC 80
#define KTOP 10
#define PRED_DIM 85
#define MAXF 2048
#define INPUT_SZ 640.0f
#define PI_F 3.14159265358979323846f

// ---------------- scratch ----------------
__device__ int    g_nf[NB];
__device__ int    g_flist[NB*MAXF];          // slot -> anchor id
__device__ int    g_cidx[NB*NA];             // anchor -> slot (written only for filtered)
__device__ float  g_cls[NB*MAXF*NC];         // 21MB: precomputed cls_cost term, [b][slot][c]
__device__ float4 g_boxc[NB*MAXF];           // compact pred boxes
__device__ float  g_costc[NB*NM*MAXF];       // 13MB compact cost (for dup resolution)
__device__ int    g_amg[NB*NA];              // packed: (count<<16) | sum_of_m
__device__ float  g_acc[NB*4];

// ---------------- helpers ----------------
__device__ __forceinline__ void anchor_geom(int a, float& xc, float& yc, float& cd){
    if (a < 6400){
        int y = a / 80, x = a - y*80;
        xc = (x + 0.5f)*8.f;  yc = (y + 0.5f)*8.f;  cd = 12.f;
    } else if (a < 8000){
        int i = a - 6400; int y = i / 40, x = i - y*40;
        xc = (x + 0.5f)*16.f; yc = (y + 0.5f)*16.f; cd = 24.f;
    } else {
        int i = a - 8000; int y = i / 20, x = i - y*20;
        xc = (x + 0.5f)*32.f; yc = (y + 0.5f)*32.f; cd = 48.f;
    }
}

__device__ __forceinline__ float sigmoid_f(float x){
    return 1.f / (1.f + __expf(-x));     // x<<0 -> inf -> 0; x>>0 -> 1
}

__device__ __forceinline__ float bce_logits(float x, float t){
    return fmaxf(x, 0.f) - x*t + log1pf(__expf(-fabsf(x)));
}

__device__ __forceinline__ float ciou_loss(float px,float py,float pw,float ph,
                                           float gx,float gy,float gw,float gh){
    const float eps = 1e-7f;
    float px1=px-pw*0.5f, py1=py-ph*0.5f, px2=px+pw*0.5f, py2=py+ph*0.5f;
    float gx1=gx-gw*0.5f, gy1=gy-gh*0.5f, gx2=gx+gw*0.5f, gy2=gy+gh*0.5f;
    float iw = fmaxf(fminf(px2,gx2)-fmaxf(px1,gx1), 0.f);
    float ih = fmaxf(fminf(py2,gy2)-fmaxf(py1,gy1), 0.f);
    float inter = iw*ih;
    float uni = pw*ph + gw*gh - inter + eps;
    float iou = inter/uni;
    float cw = fmaxf(px2,gx2)-fminf(px1,gx1);
    float ch = fmaxf(py2,gy2)-fminf(py1,gy1);
    float c2 = cw*cw + ch*ch + eps;
    float rho2 = (gx-px)*(gx-px) + (gy-py)*(gy-py);
    float d = atanf(gw/(gh+eps)) - atanf(pw/(ph+eps));
    float v = (4.0f/(PI_F*PI_F))*d*d;
    float alpha = v/(1.f-iou+v+eps);
    return 1.f - iou + rho2/c2 + alpha*v;
}

// ---------------- kernel 0: zero state ----------------
__global__ void initK(){
    int t = blockIdx.x*blockDim.x + threadIdx.x;
    if (t < NB*NA/4) ((int4*)g_amg)[t] = make_int4(0,0,0,0);
    if (t < NB*4) g_acc[t] = 0.f;
    if (t < NB)   g_nf[t] = 0;
}

// ---------------- kernel 1: geometry filter + compaction ----------------
__global__ void filterK(const float* __restrict__ tgt){
    int b = blockIdx.y;
    int a = blockIdx.x*blockDim.x + threadIdx.x;
    __shared__ float sgx[NM], sgy[NM];
    __shared__ int   svalid[NM];
    for (int i=threadIdx.x; i<NM; i+=blockDim.x){
        float c0 = tgt[(b*NM+i)*5];
        svalid[i] = c0 >= 0.f;
        sgx[i] = tgt[(b*NM+i)*5+1]*INPUT_SZ;
        sgy[i] = tgt[(b*NM+i)*5+2]*INPUT_SZ;
    }
    __syncthreads();
    if (a >= NA) return;
    float xc, yc, cd; anchor_geom(a, xc, yc, cd);
    bool any = false;
    for (int m=0; m<NM; m++){
        if (!svalid[m]) continue;
        float c_l = xc - (sgx[m] - cd);
        float c_r = (sgx[m] + cd) - xc;
        float c_t = yc - (sgy[m] - cd);
        float c_b = (sgy[m] + cd) - yc;
        if (fminf(fminf(c_l,c_r), fminf(c_t,c_b)) > 0.f){ any = true; break; }
    }
    if (!any) return;
    int slot = atomicAdd(&g_nf[b], 1);
    if (slot >= MAXF) return;                      // safety, can't occur (<=1900)
    g_flist[b*MAXF + slot] = a;
    g_cidx[b*NA + a] = slot;
}

// ---------------- kernel 2: warp-per-slot class-cost precompute ----------------
__global__ void gatherK(const float* __restrict__ pred){
    int b = blockIdx.y;
    int slot = blockIdx.x*8 + (threadIdx.x >> 5);
    int lane = threadIdx.x & 31;
    int nf = g_nf[b]; if (nf > MAXF) nf = MAXF;
    if (slot >= nf) return;
    int a = g_flist[b*MAXF + slot];
    const float* pr = pred + ((size_t)b*NA + a)*PRED_DIM;
    float sobj = sigmoid_f(pr[4]);                 // broadcast load, all lanes
    // lane handles classes lane, lane+32, lane+64(<80)
    float lp0, lp1, lp2=0.f, l1m0, l1m1, l1m2=0.f;
    {
        float p = sqrtf(sigmoid_f(pr[5+lane]) * sobj);
        lp0  = fmaxf(__logf(p),   -100.f);
        l1m0 = fmaxf(log1pf(-p),  -100.f);
    }
    {
        float p = sqrtf(sigmoid_f(pr[5+lane+32]) * sobj);
        lp1  = fmaxf(__logf(p),   -100.f);
        l1m1 = fmaxf(log1pf(-p),  -100.f);
    }
    if (lane < 16){
        float p = sqrtf(sigmoid_f(pr[5+lane+64]) * sobj);
        lp2  = fmaxf(__logf(p),   -100.f);
        l1m2 = fmaxf(log1pf(-p),  -100.f);
    }
    float s1m = l1m0 + l1m1 + l1m2;
    #pragma unroll
    for (int s=16; s>=1; s>>=1) s1m += __shfl_xor_sync(0xffffffffu, s1m, s);
    float* dst = g_cls + ((size_t)(b*MAXF + slot))*NC;
    dst[lane]      = -lp0 - (s1m - l1m0);
    dst[lane+32]   = -lp1 - (s1m - l1m1);
    if (lane < 16) dst[lane+64] = -lp2 - (s1m - l1m2);
    if (lane == 0) g_boxc[b*MAXF + slot] = make_float4(pr[0], pr[1], pr[2], pr[3]);
}

// ---------------- kernel 3: cost + top-k + scatter ----------------
__global__ void costK(const float* __restrict__ tgt){
    int bm = blockIdx.x;
    int b = bm / NM, m = bm - b*NM;
    int t = threadIdx.x;                           // 128 threads
    const float* tr = tgt + bm*5;
    float c0 = tr[0];
    if (c0 < 0.f) return;                          // padded GT
    int gcls = (int)fminf(fmaxf(c0, 0.f), (float)(NC-1));
    float gx = tr[1]*INPUT_SZ, gy = tr[2]*INPUT_SZ, gw = tr[3]*INPUT_SZ, gh = tr[4]*INPUT_SZ;
    float areag = gw*gh;
    int nf = g_nf[b]; if (nf > MAXF) nf = MAXF;

    float cv[KTOP]; int ci[KTOP]; float iv[KTOP];
    #pragma unroll
    for (int k=0;k<KTOP;k++){ cv[k]=3.4e38f; ci[k]=0x7fffffff; iv[k]=0.f; }

    const int*    flst = g_flist + b*MAXF;
    const float4* boxp = g_boxc + b*MAXF;
    const float*  clsb = g_cls + (size_t)b*MAXF*NC + gcls;
    float* crow = g_costc + (size_t)bm * MAXF;

    for (int i = t; i < nf; i += 128){
        int a = flst[i];
        float xc, yc, cd; anchor_geom(a, xc, yc, cd);
        float c_l = xc - (gx - cd);
        float c_r = (gx + cd) - xc;
        float c_t = yc - (gy - cd);
        float c_b = (gy + cd) - yc;
        bool in_c = fminf(fminf(c_l,c_r), fminf(c_t,c_b)) > 0.f;

        float4 pb = boxp[i];
        float px=pb.x, py=pb.y, pw=pb.z, ph=pb.w;
        float tlx = fmaxf(gx-gw*0.5f, px-pw*0.5f);
        float tly = fmaxf(gy-gh*0.5f, py-ph*0.5f);
        float brx = fminf(gx+gw*0.5f, px+pw*0.5f);
        float bry = fminf(gy+gh*0.5f, py+ph*0.5f);
        float iou = 0.f;
        if (tlx<brx && tly<bry){
            float ai = (brx-tlx)*(bry-tly);
            iou = ai/(areag + pw*ph - ai);
        }
        float iou_cost = -logf(iou + 1e-8f);
        float cls_cost = clsb[(size_t)i*NC];
        float cost = (cls_cost + 3.f*iou_cost) + (in_c ? 0.f : 1e6f);
        crow[i] = cost;

        if (cost < cv[KTOP-1] || (cost == cv[KTOP-1] && a < ci[KTOP-1])){
            cv[KTOP-1]=cost; ci[KTOP-1]=a;
            #pragma unroll
            for (int j=KTOP-1;j>0;j--){
                bool sw = cv[j] < cv[j-1] || (cv[j]==cv[j-1] && ci[j]<ci[j-1]);
                if (!sw) break;
                float tv=cv[j]; cv[j]=cv[j-1]; cv[j-1]=tv;
                int ti=ci[j]; ci[j]=ci[j-1]; ci[j-1]=ti;
            }
        }
        if (iou > iv[KTOP-1]){
            iv[KTOP-1]=iou;
            #pragma unroll
            for (int j=KTOP-1;j>0;j--){
                if (iv[j] <= iv[j-1]) break;
                float tv=iv[j]; iv[j]=iv[j-1]; iv[j-1]=tv;
            }
        }
    }

    __shared__ float scv[128][KTOP];
    __shared__ int   sci[128][KTOP];
    __shared__ float siv[128][KTOP];
    __shared__ int   sdk;
    #pragma unroll
    for (int k=0;k<KTOP;k++){ scv[t][k]=cv[k]; sci[t][k]=ci[k]; siv[t][k]=iv[k]; }

    for (int s=64; s>=1; s>>=1){
        __syncthreads();
        if (t < s){
            float av[KTOP], bv[KTOP], a2[KTOP], b2[KTOP]; int ai[KTOP], bi[KTOP];
            #pragma unroll
            for (int k=0;k<KTOP;k++){
                av[k]=scv[t][k];   ai[k]=sci[t][k];
                bv[k]=scv[t+s][k]; bi[k]=sci[t+s][k];
                a2[k]=siv[t][k];   b2[k]=siv[t+s][k];
            }
            int i=0, j=0;
            #pragma unroll
            for (int k=0;k<KTOP;k++){
                bool ta = av[i] < bv[j] || (av[i]==bv[j] && ai[i] < bi[j]);
                if (ta){ scv[t][k]=av[i]; sci[t][k]=ai[i]; i++; }
                else   { scv[t][k]=bv[j]; sci[t][k]=bi[j]; j++; }
            }
            i=0; j=0;
            #pragma unroll
            for (int k=0;k<KTOP;k++){
                if (a2[i] >= b2[j]) { siv[t][k]=a2[i]; i++; }
                else                { siv[t][k]=b2[j]; j++; }
            }
        }
    }
    __syncthreads();
    if (t == 0){
        float sum = 0.f;
        #pragma unroll
        for (int k=0;k<KTOP;k++) sum += siv[0][k];
        int dk = (int)sum;                          // trunc == astype(int32)
        sdk = dk < 1 ? 1 : (dk > KTOP ? KTOP : dk);
    }
    __syncthreads();
    if (t < sdk){                                   // fused scatter
        int a = sci[0][t];
        if (a >= 0 && a < NA)
            atomicAdd(&g_amg[b*NA + a], 0x10000 + m);
    }
}

// ---------------- kernel 4: losses (+ inline duplicate resolution) ----------------
__global__ void lossK(const float* __restrict__ pred, const float* __restrict__ tgt){
    int b = blockIdx.y;
    int a = blockIdx.x*blockDim.x + threadIdx.x;
    int t = threadIdx.x;
    __shared__ float stg[NM*5];
    for (int i=t; i<NM*5; i+=blockDim.x) stg[i]=tgt[b*NM*5+i];
    __syncthreads();
    float o=0.f, cl=0.f, bx=0.f, np=0.f;
    if (a < NA){
        const float* pr = pred + ((size_t)b*NA + a)*PRED_DIM;
        int v = g_amg[b*NA + a];
        int cnt = v >> 16;
        int mg = -1;
        if (cnt == 1) mg = v & 0xffff;
        else if (cnt > 1){
            int slot = g_cidx[b*NA + a];
            float best = 3.4e38f; int bi = 0;
            for (int m=0;m<NM;m++){
                if (stg[m*5] < 0.f) continue;
                float c = g_costc[((size_t)(b*NM+m))*MAXF + slot];
                if (c < best){ best=c; bi=m; }      // first-min = jnp.argmin
            }
            mg = bi;
        }
        float tf = (mg >= 0) ? 1.f : 0.f;
        o = bce_logits(pr[4], tf);
        if (mg >= 0){
            np = 1.f;
            int gc = (int)fminf(fmaxf(stg[mg*5], 0.f), (float)(NC-1));
            #pragma unroll 4
            for (int c=0;c<NC;c++)
                cl += bce_logits(pr[5+c], (c==gc)?1.f:0.f);
            float gx=stg[mg*5+1]*INPUT_SZ, gy=stg[mg*5+2]*INPUT_SZ;
            float gw=stg[mg*5+3]*INPUT_SZ, gh=stg[mg*5+4]*INPUT_SZ;
            bx = ciou_loss(pr[0],pr[1],pr[2],pr[3], gx,gy,gw,gh);
        }
    }
    // block reduction
    __shared__ float r0[256], r1[256], r2[256], r3[256];
    r0[t]=o; r1[t]=cl; r2[t]=bx; r3[t]=np;
    __syncthreads();
    for (int s=128; s>=1; s>>=1){
        if (t < s){ r0[t]+=r0[t+s]; r1[t]+=r1[t+s]; r2[t]+=r2[t+s]; r3[t]+=r3[t+s]; }
        __syncthreads();
    }
    if (t==0){
        atomicAdd(&g_acc[b*4+0], r0[0]);
        atomicAdd(&g_acc[b*4+1], r1[0]);
        atomicAdd(&g_acc[b*4+2], r2[0]);
        atomicAdd(&g_acc[b*4+3], r3[0]);
    }
}

// ---------------- kernel 5: final reduction ----------------
__global__ void finalK(float* __restrict__ out){
    int t = threadIdx.x;
    float obj=0.f, cls=0.f, box=0.f, np=0.f;
    if (t < NB){
        np  = g_acc[t*4+3];
        obj = g_acc[t*4+0] / (float)NA;
        cls = (np > 0.f) ? g_acc[t*4+1]/(np*(float)NC) : 0.f;
        box = (np > 0.f) ? g_acc[t*4+2]/np : 0.f;
    }
    for (int s=16; s>=1; s>>=1){
        obj += __shfl_down_sync(0xffffffffu, obj, s);
        cls += __shfl_down_sync(0xffffffffu, cls, s);
        box += __shfl_down_sync(0xffffffffu, box, s);
        np  += __shfl_down_sync(0xffffffffu, np,  s);
    }
    if (t==0){
        float total = (5.f*box + obj + cls) / fmaxf(np, 1.f);
        out[0]=total; out[1]=box; out[2]=obj; out[3]=cls; out[4]=np;
    }
}

// ---------------- launch ----------------
extern "C" void kernel_launch(void* const* d_in, const int* in_sizes, int n_in,
                              void* d_out, int out_size){
    const float* pred = (const float*)d_in[0];   // [B, A, 85]
    const float* tgt  = (const float*)d_in[1];   // [B, M, 5]
    float* out = (float*)d_out;                  // 5 floats

    initK<<<(NB*NA/4 + 255)/256, 256>>>();
    dim3 gA((NA+255)/256, NB);
    filterK<<<gA, 256>>>(tgt);
    gatherK<<<dim3(MAXF/8, NB), 256>>>(pred);
    costK<<<NB*NM, 128>>>(tgt);
    lossK<<<gA, 256>>>(pred, tgt);
    finalK<<<1, 32>>>(out);
}